// round 7
// baseline (speedup 1.0000x reference)
#include <cuda_runtime.h>
#include <cuda_bf16.h>
#include <stdint.h>
#include <math.h>

#define NN    2000
#define NS    1000
#define SP    1024
#define DD    128
#define HH    256
#define BPAIR 100000
#define KNEG  5
#define EPOS  200000
#define ENEG  200000

#define NPD   2048
#define KS3   384
#define KH3   768
#define NSKB  391         // ceil(100000/256)

// ---------------- scratch ----------------
__device__ __nv_bfloat16 g_Abf [SP * SP];
__device__ __nv_bfloat16 g_S1bf[SP * SP];
__device__ float         g_Gp  [SP * SP];
__device__ float         g_dsrc[SP];
__device__ float         g_ddst[SP];
__device__ __nv_bfloat16 g_Na  [NPD * KS3];
__device__ __nv_bfloat16 g_Cb  [NPD * KS3];
__device__ float         g_M   [NPD * NPD];
__device__ __nv_bfloat16 g_Hs  [SP * KH3];
__device__ __nv_bfloat16 g_Hd  [SP * KH3];
__device__ float         g_S   [SP * SP];
__device__ float         g_part[NSKB];

__device__ __forceinline__ float warp_sum(float v) {
#pragma unroll
    for (int off = 16; off; off >>= 1) v += __shfl_xor_sync(0xffffffffu, v, off);
    return v;
}
__device__ __forceinline__ uint32_t sA(const void* p) {
    return (uint32_t)__cvta_generic_to_shared(p);
}
__device__ __forceinline__ void cp16(uint32_t dst, const void* src) {
    asm volatile("cp.async.cg.shared.global [%0], [%1], 16;" :: "r"(dst), "l"(src) : "memory");
}
__device__ __forceinline__ void cp_commit() { asm volatile("cp.async.commit_group;" ::: "memory"); }
__device__ __forceinline__ void cp_wait1()  { asm volatile("cp.async.wait_group 1;" ::: "memory"); }
__device__ __forceinline__ void cp_wait0()  { asm volatile("cp.async.wait_group 0;" ::: "memory"); }
__device__ __forceinline__ void split_bf(float x, __nv_bfloat16& hi, __nv_bfloat16& lo) {
    hi = __float2bfloat16(x);
    lo = __float2bfloat16(x - __bfloat162float(hi));
}

struct SmemGemm { __nv_bfloat16 As[2][128][40]; __nv_bfloat16 Bs[2][64][40]; };
struct SmemTg   { __nv_bfloat16 As[2][128][40]; __nv_bfloat16 Bs[2][32][72]; };

// ================= front: packA ∪ degrees ∪ split-pack embeds ==========
#define FB_PACK 4096
#define FB_DSRC (FB_PACK + 128)
#define FB_DDST (FB_DSRC + 4)
#define FB_SKPK (FB_DDST + 1024)

__global__ __launch_bounds__(256) void k_front(const float* __restrict__ adj,
                                               const float* __restrict__ node_embed,
                                               const float* __restrict__ context_embed) {
    int bid = blockIdx.x, tid = threadIdx.x;
    int lane = tid & 31, wib = tid >> 5;

    if (bid < FB_PACK) {
        int idx = bid * 256 + tid;
        int i = idx >> 10, j = idx & (SP - 1);
        float v = (i < NS && j < NS) ? adj[i * NN + NS + j] : 0.f;
        g_Abf[idx] = __float2bfloat16(v);
    } else if (bid < FB_DSRC) {
        int row = (bid - FB_PACK) * 8 + wib;
        float s = 0.f;
        if (row < NS)
            for (int j = lane; j < NS; j += 32) s += adj[row * NN + NS + j];
        s = warp_sum(s);
        if (lane == 0) g_dsrc[row] = (row < NS) ? s : 0.f;
    } else if (bid < FB_DDST) {
        int j = (bid - FB_DSRC) * 256 + tid;
        float s = 0.f;
        if (j < NS)
            for (int i = 0; i < NS; i++) s += adj[i * NN + NS + j];
        g_ddst[j] = s;
    } else {
        int idx = (bid - FB_DDST) * 256 + tid;
        int r = idx >> 7, c = idx & 127;
        float xn = (r < NN) ? node_embed[r * DD + c] : 0.f;
        float xc = (r < NN) ? context_embed[r * DD + c] : 0.f;
        __nv_bfloat16 nh, nl, ch, cl;
        split_bf(xn, nh, nl);
        split_bf(xc, ch, cl);
        size_t base = (size_t)r * KS3 + c;
        g_Na[base]       = nh;  g_Na[base + 128] = nh;  g_Na[base + 256] = nl;
        g_Cb[base]       = ch;  g_Cb[base + 128] = cl;  g_Cb[base + 256] = ch;
    }
}

// ================= NT GEMM body: C[.., bn..] += A[bm..,K] @ B[bn..,K]^T ==========
__device__ __forceinline__ void gemm_nt_body(const __nv_bfloat16* __restrict__ A,
                                             const __nv_bfloat16* __restrict__ B,
                                             float* __restrict__ Cf,
                                             __nv_bfloat16* __restrict__ Cbf,
                                             int ldc, int kdim, int bm, int bn,
                                             bool out_bf16, SmemGemm& sm) {
    int tid = threadIdx.x, lane = tid & 31, wid = tid >> 5;
    int warp_m = wid >> 2, warp_n = wid & 3;
    int NIT = kdim >> 5;

    float acc[4][2][4];
#pragma unroll
    for (int i = 0; i < 4; i++)
#pragma unroll
        for (int j = 0; j < 2; j++)
#pragma unroll
            for (int r = 0; r < 4; r++) acc[i][j][r] = 0.f;

    int arow = tid >> 1, acol = (tid & 1) * 16;
    int brow = tid >> 2, bcol = (tid & 3) * 8;

    auto issue = [&](int it, int buf) {
        const __nv_bfloat16* ag = A + (size_t)(bm + arow) * kdim + it * 32 + acol;
        cp16(sA(&sm.As[buf][arow][acol]), ag);
        cp16(sA(&sm.As[buf][arow][acol + 8]), ag + 8);
        cp16(sA(&sm.Bs[buf][brow][bcol]), B + (size_t)(bn + brow) * kdim + it * 32 + bcol);
        cp_commit();
    };

    issue(0, 0);
    issue(1, 1);

    for (int it = 0; it < NIT; it++) {
        int buf = it & 1;
        if (it < NIT - 1) cp_wait1(); else cp_wait0();
        __syncthreads();
#pragma unroll
        for (int ks = 0; ks < 2; ks++) {
            uint32_t af[4][4];
#pragma unroll
            for (int mt = 0; mt < 4; mt++) {
                uint32_t addr = sA(&sm.As[buf][warp_m * 64 + mt * 16 + (lane & 15)][ks * 16 + ((lane >> 4) << 3)]);
                asm volatile("ldmatrix.sync.aligned.m8n8.x4.shared.b16 {%0,%1,%2,%3}, [%4];"
                             : "=r"(af[mt][0]), "=r"(af[mt][1]), "=r"(af[mt][2]), "=r"(af[mt][3])
                             : "r"(addr));
            }
            uint32_t bf[4];
            {
                uint32_t addr = sA(&sm.Bs[buf][warp_n * 16 + (lane & 15)][ks * 16 + ((lane >> 4) << 3)]);
                asm volatile("ldmatrix.sync.aligned.m8n8.x4.shared.b16 {%0,%1,%2,%3}, [%4];"
                             : "=r"(bf[0]), "=r"(bf[1]), "=r"(bf[2]), "=r"(bf[3])
                             : "r"(addr));
            }
#pragma unroll
            for (int mt = 0; mt < 4; mt++)
#pragma unroll
                for (int nt = 0; nt < 2; nt++) {
                    asm volatile(
                        "mma.sync.aligned.m16n8k16.row.col.f32.bf16.bf16.f32 "
                        "{%0,%1,%2,%3}, {%4,%5,%6,%7}, {%8,%9}, {%0,%1,%2,%3};"
                        : "+f"(acc[mt][nt][0]), "+f"(acc[mt][nt][1]),
                          "+f"(acc[mt][nt][2]), "+f"(acc[mt][nt][3])
                        : "r"(af[mt][0]), "r"(af[mt][1]), "r"(af[mt][2]), "r"(af[mt][3]),
                          "r"(bf[nt]), "r"(bf[nt + 2]));
                }
        }
        __syncthreads();
        if (it + 2 < NIT) issue(it + 2, buf);
    }

#pragma unroll
    for (int mt = 0; mt < 4; mt++)
#pragma unroll
        for (int nt = 0; nt < 2; nt++) {
            int row = bm + warp_m * 64 + mt * 16 + (lane >> 2);
            int col = bn + warp_n * 16 + nt * 8 + (lane & 3) * 2;
            if (out_bf16) {
                __nv_bfloat162 lo, hi;
                lo.x = __float2bfloat16(acc[mt][nt][0]); lo.y = __float2bfloat16(acc[mt][nt][1]);
                hi.x = __float2bfloat16(acc[mt][nt][2]); hi.y = __float2bfloat16(acc[mt][nt][3]);
                *(__nv_bfloat162*)&Cbf[(size_t)row * ldc + col]       = lo;
                *(__nv_bfloat162*)&Cbf[(size_t)(row + 8) * ldc + col] = hi;
            } else {
                *(float2*)&Cf[(size_t)row * ldc + col]       = make_float2(acc[mt][nt][0], acc[mt][nt][1]);
                *(float2*)&Cf[(size_t)(row + 8) * ldc + col] = make_float2(acc[mt][nt][2], acc[mt][nt][3]);
            }
        }
}

// ================= mm1: skipgram all-pairs M (512 CTAs) ∪ S1 = A A^T (128 CTAs) ==========
__global__ __launch_bounds__(256) void k_mm1() {
    __shared__ __align__(16) char smraw[sizeof(SmemGemm)];
    SmemGemm& sm = *reinterpret_cast<SmemGemm*>(smraw);
    int bid = blockIdx.x;
    if (bid < 512) {
        int bx = bid & 31, by = bid >> 5;
        gemm_nt_body(g_Na, g_Cb, g_M, nullptr, NPD, KS3, by * 128, bx * 64, false, sm);
    } else {
        int b2 = bid - 512;
        int bx = b2 & 15, by = b2 >> 4;
        gemm_nt_body(g_Abf, g_Abf, nullptr, g_S1bf, SP, SP, by * 128, bx * 64, true, sm);
    }
}

// ================= mid: P1+gamma GEMM (128 CTAs) ∪ skipgram gather (391 CTAs) ==========
__global__ __launch_bounds__(256) void k_mid(const int* __restrict__ pos_u,
                                             const int* __restrict__ pos_v,
                                             const int* __restrict__ neg_v) {
    __shared__ __align__(16) char smraw[sizeof(SmemTg)];
    int bid = blockIdx.x, tid = threadIdx.x;

    if (bid < 128) {
        SmemTg& sm = *reinterpret_cast<SmemTg*>(smraw);
        int bx = bid & 15, by = bid >> 4;
        int bm = by * 128, bn = bx * 64;
        int lane = tid & 31, wid = tid >> 5;
        int warp_m = wid >> 2, warp_n = wid & 3;
        const int NIT = SP / 32;

        float acc[4][2][4];
#pragma unroll
        for (int i = 0; i < 4; i++)
#pragma unroll
            for (int j = 0; j < 2; j++)
#pragma unroll
                for (int r = 0; r < 4; r++) acc[i][j][r] = 0.f;

        int arow = tid >> 1, acol = (tid & 1) * 16;
        int brow = tid >> 3, bcol = (tid & 7) * 8;

        auto issue = [&](int it, int buf) {
            const __nv_bfloat16* ag = g_S1bf + (size_t)(bm + arow) * SP + it * 32 + acol;
            cp16(sA(&sm.As[buf][arow][acol]), ag);
            cp16(sA(&sm.As[buf][arow][acol + 8]), ag + 8);
            cp16(sA(&sm.Bs[buf][brow][bcol]), g_Abf + (size_t)(it * 32 + brow) * SP + bn + bcol);
            cp_commit();
        };

        issue(0, 0);
        issue(1, 1);

        for (int it = 0; it < NIT; it++) {
            int buf = it & 1;
            if (it < NIT - 1) cp_wait1(); else cp_wait0();
            __syncthreads();
#pragma unroll
            for (int ks = 0; ks < 2; ks++) {
                uint32_t af[4][4];
#pragma unroll
                for (int mt = 0; mt < 4; mt++) {
                    uint32_t addr = sA(&sm.As[buf][warp_m * 64 + mt * 16 + (lane & 15)][ks * 16 + ((lane >> 4) << 3)]);
                    asm volatile("ldmatrix.sync.aligned.m8n8.x4.shared.b16 {%0,%1,%2,%3}, [%4];"
                                 : "=r"(af[mt][0]), "=r"(af[mt][1]), "=r"(af[mt][2]), "=r"(af[mt][3])
                                 : "r"(addr));
                }
                uint32_t bf[4];
                {
                    uint32_t addr = sA(&sm.Bs[buf][ks * 16 + (lane & 15)][warp_n * 16 + ((lane >> 4) << 3)]);
                    asm volatile("ldmatrix.sync.aligned.m8n8.x4.trans.shared.b16 {%0,%1,%2,%3}, [%4];"
                                 : "=r"(bf[0]), "=r"(bf[1]), "=r"(bf[2]), "=r"(bf[3])
                                 : "r"(addr));
                }
#pragma unroll
                for (int mt = 0; mt < 4; mt++)
#pragma unroll
                    for (int nt = 0; nt < 2; nt++) {
                        asm volatile(
                            "mma.sync.aligned.m16n8k16.row.col.f32.bf16.bf16.f32 "
                            "{%0,%1,%2,%3}, {%4,%5,%6,%7}, {%8,%9}, {%0,%1,%2,%3};"
                            : "+f"(acc[mt][nt][0]), "+f"(acc[mt][nt][1]),
                              "+f"(acc[mt][nt][2]), "+f"(acc[mt][nt][3])
                            : "r"(af[mt][0]), "r"(af[mt][1]), "r"(af[mt][2]), "r"(af[mt][3]),
                              "r"(bf[nt * 2]), "r"(bf[nt * 2 + 1]));
                    }
            }
            __syncthreads();
            if (it + 2 < NIT) issue(it + 2, buf);
        }

        // fused gamma epilogue
#pragma unroll
        for (int mt = 0; mt < 4; mt++) {
            int row = bm + warp_m * 64 + mt * 16 + (lane >> 2);
            float dr0 = g_dsrc[row], dr1 = g_dsrc[row + 8];
#pragma unroll
            for (int nt = 0; nt < 2; nt++) {
                int col = bn + warp_n * 16 + nt * 8 + (lane & 3) * 2;
                float dc0 = g_ddst[col], dc1 = g_ddst[col + 1];
                __nv_bfloat162 a0 = *(const __nv_bfloat162*)&g_Abf[(size_t)row * SP + col];
                __nv_bfloat162 a1 = *(const __nv_bfloat162*)&g_Abf[(size_t)(row + 8) * SP + col];
                float d00 = dr0 * dc0, d01 = dr0 * dc1, d10 = dr1 * dc0, d11 = dr1 * dc1;
                float g00 = (d00 > 0.f) ? acc[mt][nt][0] * __bfloat162float(a0.x) / d00 : 0.f;
                float g01 = (d01 > 0.f) ? acc[mt][nt][1] * __bfloat162float(a0.y) / d01 : 0.f;
                float g10 = (d10 > 0.f) ? acc[mt][nt][2] * __bfloat162float(a1.x) / d10 : 0.f;
                float g11 = (d11 > 0.f) ? acc[mt][nt][3] * __bfloat162float(a1.y) / d11 : 0.f;
                *(float2*)&g_Gp[(size_t)row * SP + col]       = make_float2(g00, g01);
                *(float2*)&g_Gp[(size_t)(row + 8) * SP + col] = make_float2(g10, g11);
            }
        }
    } else {
        // skipgram gather
        float* red = reinterpret_cast<float*>(smraw);
        int b = bid - 128;
        int t = b * 256 + tid;
        float loss = 0.f;
        if (t < BPAIR) {
            int u = pos_u[t];
            const float* Mu = g_M + (size_t)u * NPD;
            float pos = fminf(fmaxf(Mu[pos_v[t]], -10.f), 10.f);
            loss = log1pf(expf(-pos));
#pragma unroll
            for (int k = 0; k < KNEG; k++) {
                float neg = fminf(fmaxf(Mu[neg_v[t * KNEG + k]], -10.f), 10.f);
                loss += log1pf(expf(neg));
            }
        }
        red[tid] = loss;
        __syncthreads();
        for (int s = 128; s > 0; s >>= 1) {
            if (tid < s) red[tid] += red[tid + s];
            __syncthreads();
        }
        if (tid == 0) g_part[b] = red[0];
    }
}

// ================= spmm(gamma@W1,+norm,+tanh) fused with fc2+concat+split-pack ==========
__global__ __launch_bounds__(256) void k_spmm_fc2(const float* __restrict__ W1,
                                                  const float* __restrict__ b1,
                                                  const float* __restrict__ W2,
                                                  const float* __restrict__ b2,
                                                  const float* __restrict__ node_embed) {
    int b = blockIdx.x, t = threadIdx.x;
    if (b >= NN) {
        // zero-pad rows 1000..1023 of Hs and Hd (48 blocks, 768 bf16/row)
        int idx = b - NN;
        __nv_bfloat16* dst = (idx < 24) ? g_Hs : g_Hd;
        int row = NS + (idx % 24);
#pragma unroll
        for (int q = 0; q < 3; q++) dst[(size_t)row * KH3 + q * 256 + t] = __float2bfloat16(0.f);
        return;
    }

    __shared__ int   sidx[SP];
    __shared__ float sval[SP];
    __shared__ float sred[256];
    __shared__ int   sscan[256];
    __shared__ float tr[HH];
    __shared__ float s_inv;
    __shared__ int   s_total;

    bool rowmode = (b < NS);

    // ---- phase 1: load gamma row/col, sumsq + compaction ----
    float v[4];
    int   ji[4];
    if (rowmode) {
        float4 q = *(const float4*)&g_Gp[(size_t)b * SP + t * 4];
        v[0] = q.x; v[1] = q.y; v[2] = q.z; v[3] = q.w;
#pragma unroll
        for (int i = 0; i < 4; i++) ji[i] = t * 4 + i;
    } else {
        int c = b - NS;
#pragma unroll
        for (int i = 0; i < 4; i++) {
            int r = t * 4 + i;
            v[i]  = g_Gp[(size_t)r * SP + c];
            ji[i] = r;
        }
    }
    sred[t] = v[0] * v[0] + v[1] * v[1] + v[2] * v[2] + v[3] * v[3];
    int cnt = (v[0] != 0.f) + (v[1] != 0.f) + (v[2] != 0.f) + (v[3] != 0.f);
    sscan[t] = cnt;
    __syncthreads();
    for (int st = 128; st > 0; st >>= 1) {
        if (t < st) sred[t] += sred[t + st];
        __syncthreads();
    }
    for (int off = 1; off < 256; off <<= 1) {
        int x = (t >= off) ? sscan[t - off] : 0;
        __syncthreads();
        sscan[t] += x;
        __syncthreads();
    }
    if (t == 0) {
        s_inv   = 1.f / fmaxf(sqrtf(sred[0]), 1e-12f);
        s_total = sscan[255];
    }
    int pos = sscan[t] - cnt;
    __syncthreads();
#pragma unroll
    for (int i = 0; i < 4; i++) {
        if (v[i] != 0.f) {
            sidx[pos] = ji[i];
            sval[pos] = v[i];
            pos++;
        }
    }
    __syncthreads();

    // ---- phase 2: T row = tanh(sparse dot + b1), kept in shared ----
    int total = s_total;
    int w1off = rowmode ? NS : 0;
    float acc = 0.f;
    for (int p = 0; p < total; p++)
        acc += sval[p] * W1[(size_t)(w1off + sidx[p]) * HH + t];
    tr[t] = tanhf(acc * s_inv + b1[t]);
    __syncthreads();

    // ---- phase 3: fc2 (split-k over 2 halves) + concat + split-bf16 pack ----
    int j = t & 127, half = t >> 7;
    float partial = 0.f;
#pragma unroll 8
    for (int k = half * 128; k < half * 128 + 128; k++)
        partial += tr[k] * W2[k * DD + j];
    sred[t] = partial;
    __syncthreads();
    if (t < 128) {
        float s = sred[t] + sred[t + 128] + b2[t];
        float a = node_embed[b * DD + t];
        bool srcside = rowmode;
        __nv_bfloat16* dst = srcside ? g_Hs : g_Hd;
        size_t rowb = (size_t)(srcside ? b : b - NS) * KH3;
        __nv_bfloat16 ah, al, sh, sl;
        split_bf(a, ah, al);
        split_bf(s, sh, sl);
        if (srcside) {
            dst[rowb + t]       = ah;  dst[rowb + 128 + t] = sh;
            dst[rowb + 256 + t] = ah;  dst[rowb + 384 + t] = sh;
            dst[rowb + 512 + t] = al;  dst[rowb + 640 + t] = sl;
        } else {
            dst[rowb + t]       = ah;  dst[rowb + 128 + t] = sh;
            dst[rowb + 256 + t] = al;  dst[rowb + 384 + t] = sl;
            dst[rowb + 512 + t] = ah;  dst[rowb + 640 + t] = sh;
        }
    }
}

// ================= edge score GEMM ==========
__global__ __launch_bounds__(256) void k_gemmS() {
    __shared__ __align__(16) char smraw[sizeof(SmemGemm)];
    SmemGemm& sm = *reinterpret_cast<SmemGemm*>(smraw);
    int bid = blockIdx.x;
    int bx = bid & 15, by = bid >> 4;
    gemm_nt_body(g_Hs, g_Hd, g_S, nullptr, SP, KH3, by * 128, bx * 64, false, sm);
}

// ================= tail: score gather ∪ loss finalize ==========
#define TB_GATHER 1563
__global__ __launch_bounds__(256) void k_tail(const int* __restrict__ pos_src,
                                              const int* __restrict__ pos_dst,
                                              const int* __restrict__ neg_src,
                                              const int* __restrict__ neg_dst,
                                              float* __restrict__ out) {
    int bid = blockIdx.x, tid = threadIdx.x;
    if (bid < TB_GATHER) {
        int t = bid * 256 + tid;
        if (t < EPOS) {
            out[1 + t] = g_S[(size_t)pos_src[t] * SP + pos_dst[t]];
        } else if (t < EPOS + ENEG) {
            int e = t - EPOS;
            out[1 + EPOS + e] = g_S[(size_t)neg_src[e] * SP + neg_dst[e]];
        }
    } else {
        __shared__ double red[256];
        double s = 0.0;
        for (int i = tid; i < NSKB; i += 256) s += (double)g_part[i];
        red[tid] = s;
        __syncthreads();
        for (int st = 128; st > 0; st >>= 1) {
            if (tid < st) red[tid] += red[tid + st];
            __syncthreads();
        }
        if (tid == 0) out[0] = (float)(red[0] / (double)BPAIR);
    }
}

// ---------------- launch ----------------
extern "C" void kernel_launch(void* const* d_in, const int* in_sizes, int n_in,
                              void* d_out, int out_size) {
    const float* node_embed    = (const float*)d_in[0];
    const float* context_embed = (const float*)d_in[1];
    const float* adj           = (const float*)d_in[2];
    const float* W1            = (const float*)d_in[3];
    const float* b1            = (const float*)d_in[4];
    const float* W2            = (const float*)d_in[5];
    const float* b2            = (const float*)d_in[6];
    const int*   pos_u         = (const int*)d_in[7];
    const int*   pos_v         = (const int*)d_in[8];
    const int*   neg_v         = (const int*)d_in[9];
    const int*   pos_src       = (const int*)d_in[10];
    const int*   pos_dst       = (const int*)d_in[11];
    const int*   neg_src       = (const int*)d_in[12];
    const int*   neg_dst       = (const int*)d_in[13];
    float* out = (float*)d_out;

    k_front<<<FB_SKPK, 256>>>(adj, node_embed, context_embed);
    k_mm1<<<640, 256>>>();
    k_mid<<<128 + NSKB, 256>>>(pos_u, pos_v, neg_v);
    k_spmm_fc2<<<NN + 48, 256>>>(W1, b1, W2, b2, node_embed);
    k_gemmS<<<128, 256>>>();
    k_tail<<<TB_GATHER + 1, 256>>>(pos_src, pos_dst, neg_src, neg_dst, out);
}